// round 1
// baseline (speedup 1.0000x reference)
#include <cuda_runtime.h>
#include <cstdint>
#include <cstddef>

#define BATCH   4096
#define FF      64
#define DD      256
#define PAIRS   2016
#define BPC     7              // batches per CTA
#define KC      32             // K-chunk
#define NCHUNK  (DD / KC)      // 8
#define THREADS 256
#define BATCH_WORDS (FF * KC)          // 2048 words per batch per chunk
#define CHUNK_WORDS (BPC * BATCH_WORDS) // 14336
#define SMEM_BYTES  (2 * CHUNK_WORDS * 4) // 114688 B (double buffered)

// 36 upper-triangular 8x8 tiles of the 8x8 tile grid (ti <= tj), row-major.
__constant__ int c_TI[36] = {
    0,0,0,0,0,0,0,0,
    1,1,1,1,1,1,1,
    2,2,2,2,2,2,
    3,3,3,3,3,
    4,4,4,4,
    5,5,5,
    6,6,
    7
};
__constant__ int c_TJ[36] = {
    0,1,2,3,4,5,6,7,
    1,2,3,4,5,6,7,
    2,3,4,5,6,7,
    3,4,5,6,7,
    4,5,6,7,
    5,6,7,
    6,7,
    7
};

// Packed dual-fp32 FMA (Blackwell f32x2 pipe; ptxas never emits this from C++).
__device__ __forceinline__ void ffma2(unsigned long long& d,
                                      unsigned long long a,
                                      unsigned long long b) {
    asm("fma.rn.f32x2 %0, %1, %2, %0;" : "+l"(d) : "l"(a), "l"(b));
}

__device__ __forceinline__ void cp_async8(uint32_t dst_smem, const void* src) {
    asm volatile("cp.async.ca.shared.global [%0], [%1], 8;"
                 :: "r"(dst_smem), "l"(src) : "memory");
}
__device__ __forceinline__ void cp_commit() {
    asm volatile("cp.async.commit_group;" ::: "memory");
}
template <int N>
__device__ __forceinline__ void cp_wait() {
    asm volatile("cp.async.wait_group %0;" :: "n"(N) : "memory");
}

extern __shared__ float s_buf[];

// Issue async loads of one K-chunk for nb batches into buffer `buf`.
// SMEM layout per batch: row f is KC words, element k stored at column
// (k ^ (2*(f>>3))) -> per-row XOR swizzle keeps the 8 distinct row-tile
// addresses of a compute LDS.64 on distinct bank-pairs.
__device__ __forceinline__ void issue_chunk(const float* __restrict__ in,
                                            int b0, int nb, int chunk,
                                            uint32_t smem_base, int buf) {
    const int total = nb * FF * (KC / 2);          // float2 copies
    uint32_t dstb = smem_base + (uint32_t)(buf * CHUNK_WORDS * 4);
    for (int idx = threadIdx.x; idx < total; idx += THREADS) {
        int k2 = idx & 15;                // 16 float2 per row
        int f  = (idx >> 4) & 63;
        int bl = idx >> 10;
        const float* src = in + (((size_t)(b0 + bl) * FF + f) * DD
                                 + chunk * KC + 2 * k2);
        int word = bl * BATCH_WORDS + f * KC + ((2 * k2) ^ (2 * (f >> 3)));
        cp_async8(dstb + (uint32_t)(word * 4), src);
    }
    cp_commit();
}

__global__ void __launch_bounds__(THREADS, 1)
gram_upper_kernel(const float* __restrict__ in, float* __restrict__ out) {
    const int tid = threadIdx.x;
    const int b0  = blockIdx.x * BPC;
    const int nb  = min(BPC, BATCH - b0);

    // job mapping: thread -> (batch-local, tile)
    const int bl   = tid / 36;
    const int tile = tid - bl * 36;
    const bool active = (bl < nb);          // bl<7 implies tid<252
    const int ti = c_TI[tile & 31 | (tile & 32)];  // plain index, tile<36 guaranteed
    const int tj = c_TJ[tile & 31 | (tile & 32)];

    unsigned long long acc[64];
#pragma unroll
    for (int i = 0; i < 64; i++) acc[i] = 0ull;

    uint32_t smem_base = (uint32_t)__cvta_generic_to_shared(s_buf);

    issue_chunk(in, b0, nb, 0, smem_base, 0);

    for (int c = 0; c < NCHUNK; c++) {
        if (c + 1 < NCHUNK) {
            issue_chunk(in, b0, nb, c + 1, smem_base, (c + 1) & 1);
            cp_wait<1>();
        } else {
            cp_wait<0>();
        }
        __syncthreads();

        if (active) {
            const float* buf = s_buf + (c & 1) * CHUNK_WORDS + bl * BATCH_WORDS;
            const float* Ap = buf + ti * 8 * KC;
            const float* Bp = buf + tj * 8 * KC;
            const int sa = 2 * ti;
            const int sb = 2 * tj;
#pragma unroll 4
            for (int kk = 0; kk < KC; kk += 2) {
                const int ka = kk ^ sa;
                const int kb = kk ^ sb;
                unsigned long long av[8], bv[8];
#pragma unroll
                for (int r = 0; r < 8; r++)
                    av[r] = *reinterpret_cast<const unsigned long long*>(
                        Ap + r * KC + ka);
#pragma unroll
                for (int cc = 0; cc < 8; cc++)
                    bv[cc] = *reinterpret_cast<const unsigned long long*>(
                        Bp + cc * KC + kb);
#pragma unroll
                for (int r = 0; r < 8; r++)
#pragma unroll
                    for (int cc = 0; cc < 8; cc++)
                        ffma2(acc[r * 8 + cc], av[r], bv[cc]);
            }
        }
        __syncthreads();
    }

    if (active) {
        float* ob = out + (size_t)(b0 + bl) * PAIRS;
#pragma unroll
        for (int r = 0; r < 8; r++) {
            const int i = ti * 8 + r;
#pragma unroll
            for (int cc = 0; cc < 8; cc++) {
                const int j = tj * 8 + cc;
                if (j > i) {
                    unsigned long long v = acc[r * 8 + cc];
                    float lo = __int_as_float((unsigned)(v & 0xffffffffull));
                    float hi = __int_as_float((unsigned)(v >> 32));
                    // row-major strict-upper linear index
                    ob[i * FF - (i * (i + 1)) / 2 + (j - i - 1)] = lo + hi;
                }
            }
        }
    }
}

extern "C" void kernel_launch(void* const* d_in, const int* in_sizes, int n_in,
                              void* d_out, int out_size) {
    const float* in = (const float*)d_in[0];
    float* out = (float*)d_out;
    (void)in_sizes; (void)n_in; (void)out_size;

    // >48KB dynamic smem opt-in (idempotent; not a stream op, capture-safe)
    cudaFuncSetAttribute(gram_upper_kernel,
                         cudaFuncAttributeMaxDynamicSharedMemorySize,
                         SMEM_BYTES);

    const int grid = (BATCH + BPC - 1) / BPC;  // 586
    gram_upper_kernel<<<grid, THREADS, SMEM_BYTES>>>(in, out);
}

// round 3
// speedup vs baseline: 2.7023x; 2.7023x over previous
#include <cuda_runtime.h>
#include <cstdint>
#include <cstddef>

#define BATCH   4096
#define FFI     64
#define DDIM    256
#define PAIRS   2016
#define THREADS 128
#define KC      64            // K elements per chunk
#define NCH     (DDIM / KC)   // 4
#define SROW    68            // padded smem row stride (words)

// per-warp tile config: 20 upper-triangular m16n8 tiles of the 64x64 gram,
// 5 per warp; each warp touches at most 2 distinct 16-row A strips.
__device__ constexpr int cMI0[4]     = {0, 0, 1, 2};
__device__ constexpr int cMI1[4]     = {0, 1, 2, 3};
__device__ constexpr int cNJ[4][5]   = {{0,1,2,3,4},{5,6,7,2,3},{4,5,6,7,4},{5,6,7,6,7}};
__device__ constexpr int cSEL[4][5]  = {{0,0,0,0,0},{0,0,0,1,1},{0,0,0,0,1},{0,0,0,1,1}};

__device__ __forceinline__ uint32_t f2tf32(float x) {
    uint32_t r;
    asm("cvt.rna.tf32.f32 %0, %1;" : "=r"(r) : "f"(x));
    return r;
}

__device__ __forceinline__ void mma8(float& d0, float& d1, float& d2, float& d3,
                                     uint32_t a0, uint32_t a1, uint32_t a2, uint32_t a3,
                                     uint32_t b0, uint32_t b1) {
    asm("mma.sync.aligned.m16n8k8.row.col.f32.tf32.tf32.f32 "
        "{%0,%1,%2,%3}, {%4,%5,%6,%7}, {%8,%9}, {%0,%1,%2,%3};"
        : "+f"(d0), "+f"(d1), "+f"(d2), "+f"(d3)
        : "r"(a0), "r"(a1), "r"(a2), "r"(a3), "r"(b0), "r"(b1));
}

template <int W>
__device__ __forceinline__ void chunk_mma(const uint32_t* __restrict__ sb,
                                          int lid, float (&acc)[20]) {
    const int grp = lid >> 2, quad = lid & 3;
#pragma unroll
    for (int ks = 0; ks < KC / 8; ks++) {
        const int k = ks * 8 + quad;
        uint32_t a0[4], a1[4];
        {
            const uint32_t* p = sb + (cMI0[W] * 16 + grp) * SROW + k;
            a0[0] = p[0]; a0[2] = p[4];
            a0[1] = p[8 * SROW]; a0[3] = p[8 * SROW + 4];
        }
        if constexpr (cMI1[W] != cMI0[W]) {
            const uint32_t* p = sb + (cMI1[W] * 16 + grp) * SROW + k;
            a1[0] = p[0]; a1[2] = p[4];
            a1[1] = p[8 * SROW]; a1[3] = p[8 * SROW + 4];
        } else {
            a1[0] = a0[0]; a1[1] = a0[1]; a1[2] = a0[2]; a1[3] = a0[3];
        }
#pragma unroll
        for (int t = 0; t < 5; t++) {
            const uint32_t* q = sb + (cNJ[W][t] * 8 + grp) * SROW + k;
            const uint32_t b0 = q[0], b1 = q[4];
            if constexpr (true) {
                if (cSEL[W][t] == 0)   // constexpr-foldable
                    mma8(acc[4*t], acc[4*t+1], acc[4*t+2], acc[4*t+3],
                         a0[0], a0[1], a0[2], a0[3], b0, b1);
                else
                    mma8(acc[4*t], acc[4*t+1], acc[4*t+2], acc[4*t+3],
                         a1[0], a1[1], a1[2], a1[3], b0, b1);
            }
        }
    }
}

__device__ __forceinline__ void stp(float* __restrict__ ob, int i, int j,
                                    float v, bool need_check) {
    if (!need_check || j > i)
        ob[i * FFI - (i * (i + 1)) / 2 + j - i - 1] = v;
}

template <int W>
__device__ __forceinline__ void epilogue(const float (&acc)[20], int lid,
                                         float* __restrict__ ob) {
    const int grp = lid >> 2, quad = lid & 3;
#pragma unroll
    for (int t = 0; t < 5; t++) {
        const int mi = cSEL[W][t] ? cMI1[W] : cMI0[W];
        const int nj = cNJ[W][t];
        const bool chk = (nj < 2 * mi + 2);   // tile straddles the diagonal
        const int i0 = mi * 16 + grp, i1 = i0 + 8;
        const int j0 = nj * 8 + 2 * quad, j1 = j0 + 1;
        stp(ob, i0, j0, acc[4*t + 0], chk);
        stp(ob, i0, j1, acc[4*t + 1], chk);
        stp(ob, i1, j0, acc[4*t + 2], chk);
        stp(ob, i1, j1, acc[4*t + 3], chk);
    }
}

__global__ void __launch_bounds__(THREADS, 1)
gram_mma_kernel(const float* __restrict__ in, float* __restrict__ out) {
    __shared__ __align__(16) uint32_t sb[2][FFI * SROW];

    const int tid = threadIdx.x;
    const int wid = tid >> 5, lid = tid & 31;
    const int b = blockIdx.x;

    const float4* src = reinterpret_cast<const float4*>(in)
                        + (size_t)b * FFI * (DDIM / 4);
    const int lrow = tid >> 4;      // 0..7 row-within-group-of-8
    const int lcol = tid & 15;      // float4 column within chunk

    float4 regs[8];
    auto load_chunk = [&](int c) {
#pragma unroll
        for (int i = 0; i < 8; i++) {
            const int r = i * 8 + lrow;
            regs[i] = __ldg(src + (size_t)r * (DDIM / 4) + c * (KC / 4) + lcol);
        }
    };
    auto store_chunk = [&](int buf) {
#pragma unroll
        for (int i = 0; i < 8; i++) {
            const int r = i * 8 + lrow;
            uint4 v;
            v.x = f2tf32(regs[i].x); v.y = f2tf32(regs[i].y);
            v.z = f2tf32(regs[i].z); v.w = f2tf32(regs[i].w);
            *reinterpret_cast<uint4*>(&sb[buf][r * SROW + lcol * 4]) = v;
        }
    };

    float acc[20];
#pragma unroll
    for (int i = 0; i < 20; i++) acc[i] = 0.0f;

    load_chunk(0);
    for (int c = 0; c < NCH; c++) {
        store_chunk(c & 1);
        __syncthreads();
        if (c + 1 < NCH) load_chunk(c + 1);
        const uint32_t* buf = sb[c & 1];
        switch (wid) {
            case 0:  chunk_mma<0>(buf, lid, acc); break;
            case 1:  chunk_mma<1>(buf, lid, acc); break;
            case 2:  chunk_mma<2>(buf, lid, acc); break;
            default: chunk_mma<3>(buf, lid, acc); break;
        }
        // no trailing barrier needed: next iteration writes the other buffer,
        // and the post-STS barrier orders reuse two iterations apart.
        __syncthreads();
    }

    float* ob = out + (size_t)b * PAIRS;
    switch (wid) {
        case 0:  epilogue<0>(acc, lid, ob); break;
        case 1:  epilogue<1>(acc, lid, ob); break;
        case 2:  epilogue<2>(acc, lid, ob); break;
        default: epilogue<3>(acc, lid, ob); break;
    }
}

extern "C" void kernel_launch(void* const* d_in, const int* in_sizes, int n_in,
                              void* d_out, int out_size) {
    const float* in = (const float*)d_in[0];
    float* out = (float*)d_out;
    (void)in_sizes; (void)n_in; (void)out_size;
    gram_mma_kernel<<<BATCH, THREADS>>>(in, out);
}